// round 16
// baseline (speedup 1.0000x reference)
#include <cuda_runtime.h>
#include <cuda_bf16.h>
#include <cstdint>

#define MAX_NODES 50000
#define MAX_EDGES 800000
#define SA 132            // As row stride (floats)
#define WROW 132          // packed-W row stride (float2)
#define CHUNK_F2 (16 * WROW)        // float2 per 32-k-row chunk = 2112
#define CHUNK_B  (CHUNK_F2 * 8)     // bytes per chunk = 16896
#define CHUNK_16 (CHUNK_B / 16)     // 16B copies per chunk = 1056

// ---------------- device scratch ----------------
__device__ int   g_is64;
__device__ int   g_deg[MAX_NODES + 1];
__device__ int   g_rowptr[MAX_NODES + 1];
__device__ int   g_cursor[MAX_NODES];
__device__ int   g_csr_src[MAX_EDGES];
__device__ int   g_bsum[64];

// pre-packed tf32 weights (float2 pairs matching mma B fragment)
__device__ __align__(16) float2 g_wp1[16 * CHUNK_F2];   // 4 W x 4 chunks
__device__ __align__(16) float2 g_wp2[4 * CHUNK_F2];    // concat W, 4 chunks

// layer 1: q packed bf16; k/v interleaved per-lane {k0,k1,v0,v1}; skip/h1 fp32
__device__ __align__(16) unsigned g_q1b[MAX_NODES * 64];
__device__ uint4    g_kv1[MAX_NODES * 32];
__device__ float    g_s1[MAX_NODES * 128];
__device__ float    g_h1[MAX_NODES * 128];

// layer 2
__device__ __align__(16) unsigned g_q2b[MAX_NODES * 16];
__device__ uint4    g_kv2[MAX_NODES * 8];
__device__ float    g_s2[MAX_NODES * 32];

__device__ float g_part[((MAX_NODES + 31) / 32) * 32];

// ---------------- helpers ----------------
__device__ __forceinline__ unsigned pack_bf2(float a, float b) {
    __nv_bfloat162 h = __floats2bfloat162_rn(a, b);
    return *(unsigned*)&h;
}
__device__ __forceinline__ float2 unpack_bf2(unsigned u) {
    __nv_bfloat162 h = *(__nv_bfloat162*)&u;
    return __bfloat1622float2(h);
}
__device__ __forceinline__ float f2tf(float f) {
    unsigned u;
    asm("cvt.rna.tf32.f32 %0, %1;" : "=r"(u) : "f"(f));
    return __uint_as_float(u);
}
__device__ __forceinline__ void mma_tf32(float* c, const unsigned* a, const unsigned* b) {
    asm volatile("mma.sync.aligned.m16n8k8.row.col.f32.tf32.tf32.f32 "
                 "{%0,%1,%2,%3}, {%4,%5,%6,%7}, {%8,%9}, {%0,%1,%2,%3};"
                 : "+f"(c[0]), "+f"(c[1]), "+f"(c[2]), "+f"(c[3])
                 : "r"(a[0]), "r"(a[1]), "r"(a[2]), "r"(a[3]), "r"(b[0]), "r"(b[1]));
}
__device__ __forceinline__ void cp16(void* smem, const void* gmem) {
    unsigned sa = (unsigned)__cvta_generic_to_shared(smem);
    asm volatile("cp.async.cg.shared.global [%0], [%1], 16;" :: "r"(sa), "l"(gmem));
}
#define CP_COMMIT() asm volatile("cp.async.commit_group;")
#define CP_WAIT0()  asm volatile("cp.async.wait_group 0;")

// read-only uint4 load with evict-last L1 policy (kv rows are cross-warp reused)
__device__ __forceinline__ uint4 ld_kv(const uint4* p) {
    uint4 v;
    asm volatile("ld.global.nc.L1::evict_last.v4.u32 {%0,%1,%2,%3}, [%4];"
                 : "=r"(v.x), "=r"(v.y), "=r"(v.z), "=r"(v.w) : "l"(p));
    return v;
}

// ---------------- weight pre-pack ----------------
__global__ void prepack1(const float* __restrict__ W0, const float* __restrict__ W1,
                         const float* __restrict__ W2, const float* __restrict__ W3) {
    int i = blockIdx.x * blockDim.x + threadIdx.x;      // 4*4*16*128
    if (i >= 4 * 4 * 16 * 128) return;
    int col = i & 127, r16 = (i >> 7) & 15, ch = (i >> 11) & 3, w = i >> 13;
    int kk = r16 >> 2, tig = r16 & 3;
    int kr = ch * 32 + kk * 8 + tig;
    const float* Wl[4] = {W0, W1, W2, W3};
    const float* W = Wl[w];
    g_wp1[((w * 4 + ch) * 16 + r16) * WROW + col] =
        make_float2(f2tf(W[(size_t)kr * 128 + col]), f2tf(W[(size_t)(kr + 4) * 128 + col]));
}

__global__ void prepack2(const float* __restrict__ W0, const float* __restrict__ W1,
                         const float* __restrict__ W2, const float* __restrict__ W3) {
    int i = blockIdx.x * blockDim.x + threadIdx.x;      // 4*16*128
    if (i >= 4 * 16 * 128) return;
    int col = i & 127, r16 = (i >> 7) & 15, ch = i >> 11;
    int kk = r16 >> 2, tig = r16 & 3;
    int kr = ch * 32 + kk * 8 + tig;
    const float* Wl[4] = {W0, W1, W2, W3};
    int mat = col >> 5, lc = col & 31;
    const float* W = Wl[mat];
    g_wp2[(ch * 16 + r16) * WROW + col] =
        make_float2(f2tf(W[(size_t)kr * 32 + lc]), f2tf(W[(size_t)(kr + 4) * 32 + lc]));
}

// ---------------- preprocessing ----------------
__global__ void init_kernel(const int* __restrict__ ei, int n) {
    int i = blockIdx.x * blockDim.x + threadIdx.x;
    if (i == 0) {
        int all_zero_hi = 1;
        for (int j = 0; j < 64; j++)
            if (ei[2 * j + 1] != 0) all_zero_hi = 0;
        g_is64 = all_zero_hi;
    }
    if (i <= n) g_deg[i] = 0;
}

__global__ void hist_kernel(const void* __restrict__ ei, int E) {
    int e = blockIdx.x * blockDim.x + threadIdx.x;
    if (e >= E) return;
    int d;
    if (g_is64) d = (int)((const long long*)ei)[E + e];
    else        d = ((const int*)ei)[E + e];
    atomicAdd(&g_deg[d], 1);
}

__global__ void scan_phase1(int n) {
    __shared__ int wsum[8];
    __shared__ int woff[8];
    int t = threadIdx.x, lane = t & 31, warp = t >> 5;
    int base = blockIdx.x * 2048 + t * 8;
    int v[8], s = 0;
    #pragma unroll
    for (int i = 0; i < 8; i++) {
        int idx = base + i;
        int x = (idx < n) ? g_deg[idx] : 0;
        v[i] = s;
        s += x;
    }
    int x = s;
    #pragma unroll
    for (int o = 1; o < 32; o <<= 1) {
        int y = __shfl_up_sync(0xffffffffu, x, o);
        if (lane >= o) x += y;
    }
    if (lane == 31) wsum[warp] = x;
    __syncthreads();
    if (t == 0) {
        int run = 0;
        #pragma unroll
        for (int j = 0; j < 8; j++) { int tmp = wsum[j]; woff[j] = run; run += tmp; }
        g_bsum[blockIdx.x] = run;
    }
    __syncthreads();
    int off = woff[warp] + (x - s);
    #pragma unroll
    for (int i = 0; i < 8; i++) {
        int idx = base + i;
        if (idx < n) g_rowptr[idx] = off + v[i];
    }
}

__global__ void scan_phase3(int n, int nb) {
    __shared__ int boff[33];
    int t = threadIdx.x;
    if (t < 32) {
        int v = (t < nb) ? g_bsum[t] : 0;
        int x = v;
        #pragma unroll
        for (int o = 1; o < 32; o <<= 1) {
            int y = __shfl_up_sync(0xffffffffu, x, o);
            if (t >= o) x += y;
        }
        boff[t] = x - v;
        if (t == 31) boff[32] = x;
    }
    __syncthreads();
    int idx = blockIdx.x * blockDim.x + t;
    if (idx < n) {
        int val = g_rowptr[idx] + boff[idx >> 11];
        g_rowptr[idx] = val;
        g_cursor[idx] = val;
    }
    if (idx == 0) g_rowptr[n] = boff[32];
}

__global__ void fill_kernel(const void* __restrict__ ei, int E) {
    int e = blockIdx.x * blockDim.x + threadIdx.x;
    if (e >= E) return;
    int s, d;
    if (g_is64) {
        const long long* p = (const long long*)ei;
        s = (int)p[e];
        d = (int)p[E + e];
    } else {
        const int* p = (const int*)ei;
        s = p[e];
        d = p[E + e];
    }
    int pos = atomicAdd(&g_cursor[d], 1);
    g_csr_src[pos] = s;
}

// ---------------- mma on one 32-k-row chunk; warp tile 32(m) x 32(n) ------
__device__ __forceinline__ void mma_chunk(const float* As, const float2* Wc,
                                          int kbase, int warp_m, int warp_n,
                                          int lane, float c[2][4][4]) {
    int gid = lane >> 2, tig = lane & 3;
    const float* ab = &As[(warp_m * 32 + gid) * SA];
    #pragma unroll
    for (int kk = 0; kk < 4; kk++) {
        int kc0 = kbase + kk * 8 + tig;
        unsigned a0[4], a1[4];
        a0[0] = __float_as_uint(ab[kc0]);
        a0[1] = __float_as_uint(ab[8 * SA + kc0]);
        a0[2] = __float_as_uint(ab[kc0 + 4]);
        a0[3] = __float_as_uint(ab[8 * SA + kc0 + 4]);
        a1[0] = __float_as_uint(ab[16 * SA + kc0]);
        a1[1] = __float_as_uint(ab[24 * SA + kc0]);
        a1[2] = __float_as_uint(ab[16 * SA + kc0 + 4]);
        a1[3] = __float_as_uint(ab[24 * SA + kc0 + 4]);
        const float2* wrow = &Wc[(kk * 4 + tig) * WROW + warp_n * 32 + gid];
        #pragma unroll
        for (int nt = 0; nt < 4; nt++) {
            float2 bv = wrow[nt * 8];
            unsigned b[2] = {__float_as_uint(bv.x), __float_as_uint(bv.y)};
            mma_tf32(c[0][nt], a0, b);
            mma_tf32(c[1][nt], a1, b);
        }
    }
}

__device__ __forceinline__ void stage_chunk(const float2* __restrict__ src, float2* dst, int t) {
    const char* s = (const char*)src;
    char* d = (char*)dst;
    #pragma unroll
    for (int i = t; i < CHUNK_16; i += 256)
        cp16(d + i * 16, s + i * 16);
    CP_COMMIT();
}

// ---------------- GEMM layer 1: BM=64, w = blockIdx.y ----------------------
__global__ __launch_bounds__(256, 3) void gemm_l1(
    const float* __restrict__ A,
    const float* __restrict__ b0, const float* __restrict__ b1,
    const float* __restrict__ b2, const float* __restrict__ b3,
    unsigned* __restrict__ oq, unsigned* __restrict__ kv,
    float* __restrict__ os, int M)
{
    extern __shared__ float smf[];
    float* As = smf;                               // 64 x SA
    float2* Wb = (float2*)(smf + 64 * SA);         // 2 x CHUNK_F2

    int t = threadIdx.x, lane = t & 31, wid = t >> 5;
    int warp_m = wid & 1, warp_n = wid >> 1;
    int row0 = blockIdx.x * 64;
    int w = blockIdx.y;

    stage_chunk(g_wp1 + (w * 4) * CHUNK_F2, Wb, t);   // chunk 0 -> buf 0

    for (int i = t; i < 64 * 32; i += 256) {
        int r = i >> 5, c4 = i & 31;
        float4 v = make_float4(0.f, 0.f, 0.f, 0.f);
        if (row0 + r < M) v = *(const float4*)&A[(size_t)(row0 + r) * 128 + c4 * 4];
        *(float4*)&As[r * SA + c4 * 4] =
            make_float4(f2tf(v.x), f2tf(v.y), f2tf(v.z), f2tf(v.w));
    }

    const float* bl[4] = {b0, b1, b2, b3};

    float c[2][4][4];
    #pragma unroll
    for (int i = 0; i < 2; i++)
        #pragma unroll
        for (int j = 0; j < 4; j++)
            #pragma unroll
            for (int q = 0; q < 4; q++) c[i][j][q] = 0.f;

    #pragma unroll
    for (int kc = 0; kc < 4; kc++) {
        CP_WAIT0();
        __syncthreads();
        if (kc < 3)
            stage_chunk(g_wp1 + (w * 4 + kc + 1) * CHUNK_F2,
                        Wb + ((kc + 1) & 1) * CHUNK_F2, t);
        mma_chunk(As, Wb + (kc & 1) * CHUNK_F2, kc * 32, warp_m, warp_n, lane, c);
    }

    #pragma unroll
    for (int mt = 0; mt < 2; mt++) {
        #pragma unroll
        for (int nt = 0; nt < 4; nt++) {
            int rg = row0 + warp_m * 32 + mt * 16 + (lane >> 2);
            int col = warp_n * 32 + nt * 8 + (lane & 3) * 2;
            int u = col >> 1;
            float2 bb = *(const float2*)&bl[w][col];
            float x0 = c[mt][nt][0] + bb.x, x1 = c[mt][nt][1] + bb.y;
            float x2 = c[mt][nt][2] + bb.x, x3 = c[mt][nt][3] + bb.y;
            if (w == 0) {
                if (rg < M)     oq[(size_t)rg * 64 + u] = pack_bf2(x0, x1);
                if (rg + 8 < M) oq[(size_t)(rg + 8) * 64 + u] = pack_bf2(x2, x3);
            } else if (w < 3) {
                int off = (u >> 1) * 4 + (u & 1) + ((w == 1) ? 0 : 2);
                if (rg < M)     kv[(size_t)rg * 128 + off] = pack_bf2(x0, x1);
                if (rg + 8 < M) kv[(size_t)(rg + 8) * 128 + off] = pack_bf2(x2, x3);
            } else {
                if (rg < M)     *(float2*)&os[(size_t)rg * 128 + col] = make_float2(x0, x1);
                if (rg + 8 < M) *(float2*)&os[(size_t)(rg + 8) * 128 + col] = make_float2(x2, x3);
            }
        }
    }
}

// ---------------- GEMM layer 2: BM=64, K=128, concat W ---------------------
__global__ __launch_bounds__(256, 3) void gemm_l2(
    const float* __restrict__ A,
    const float* __restrict__ b0, const float* __restrict__ b1,
    const float* __restrict__ b2, const float* __restrict__ b3,
    unsigned* __restrict__ oq, unsigned* __restrict__ kv,
    float* __restrict__ os, int M)
{
    extern __shared__ float smf[];
    float* As = smf;
    float2* Wb = (float2*)(smf + 64 * SA);

    int t = threadIdx.x, lane = t & 31, wid = t >> 5;
    int warp_m = wid & 1, warp_n = wid >> 1;
    int row0 = blockIdx.x * 64;

    stage_chunk(g_wp2, Wb, t);

    for (int i = t; i < 64 * 32; i += 256) {
        int r = i >> 5, c4 = i & 31;
        float4 v = make_float4(0.f, 0.f, 0.f, 0.f);
        if (row0 + r < M) v = *(const float4*)&A[(size_t)(row0 + r) * 128 + c4 * 4];
        *(float4*)&As[r * SA + c4 * 4] =
            make_float4(f2tf(v.x), f2tf(v.y), f2tf(v.z), f2tf(v.w));
    }

    const float* bl[4] = {b0, b1, b2, b3};

    float c[2][4][4];
    #pragma unroll
    for (int i = 0; i < 2; i++)
        #pragma unroll
        for (int j = 0; j < 4; j++)
            #pragma unroll
            for (int q = 0; q < 4; q++) c[i][j][q] = 0.f;

    #pragma unroll
    for (int ch = 0; ch < 4; ch++) {
        CP_WAIT0();
        __syncthreads();
        if (ch < 3)
            stage_chunk(g_wp2 + (ch + 1) * CHUNK_F2, Wb + ((ch + 1) & 1) * CHUNK_F2, t);
        mma_chunk(As, Wb + (ch & 1) * CHUNK_F2, ch * 32, warp_m, warp_n, lane, c);
    }

    // mat == warp_n (each 32-col group is one matrix)
    #pragma unroll
    for (int mt = 0; mt < 2; mt++) {
        #pragma unroll
        for (int nt = 0; nt < 4; nt++) {
            int rg = row0 + warp_m * 32 + mt * 16 + (lane >> 2);
            int lc = nt * 8 + (lane & 3) * 2;
            int u = lc >> 1;
            float2 bb = *(const float2*)&bl[warp_n][lc];
            float x0 = c[mt][nt][0] + bb.x, x1 = c[mt][nt][1] + bb.y;
            float x2 = c[mt][nt][2] + bb.x, x3 = c[mt][nt][3] + bb.y;
            if (warp_n == 0) {
                if (rg < M)     oq[(size_t)rg * 16 + u] = pack_bf2(x0, x1);
                if (rg + 8 < M) oq[(size_t)(rg + 8) * 16 + u] = pack_bf2(x2, x3);
            } else if (warp_n < 3) {
                int off = (u >> 1) * 4 + (u & 1) + ((warp_n == 1) ? 0 : 2);
                if (rg < M)     kv[(size_t)rg * 32 + off] = pack_bf2(x0, x1);
                if (rg + 8 < M) kv[(size_t)(rg + 8) * 32 + off] = pack_bf2(x2, x3);
            } else {
                if (rg < M)     *(float2*)&os[(size_t)rg * 32 + lc] = make_float2(x0, x1);
                if (rg + 8 < M) *(float2*)&os[(size_t)(rg + 8) * 32 + lc] = make_float2(x2, x3);
            }
        }
    }
}

// ---------------- fused edge attention, layer 1 (4 heads x 32) -------------
// x4 unroll with pipelined index prefetch; kv loads use evict_last policy
__device__ __forceinline__ void attn1_edge(const uint4* kvp, int s, int lane,
                                           float2 q01, float2 q23,
                                           float4& acc, float& den) {
    uint4 kv0 = ld_kv(&kvp[(size_t)s * 32 + lane]);
    float2 ka = unpack_bf2(kv0.x), kb = unpack_bf2(kv0.y);
    float d = q01.x * ka.x + q01.y * ka.y + q23.x * kb.x + q23.y * kb.y;
    d += __shfl_xor_sync(0xffffffffu, d, 1);
    d += __shfl_xor_sync(0xffffffffu, d, 2);
    d += __shfl_xor_sync(0xffffffffu, d, 4);
    float p = __expf(d * 0.17677669529663689f);
    den += p;
    float2 va = unpack_bf2(kv0.z), vb = unpack_bf2(kv0.w);
    acc.x += p * va.x; acc.y += p * va.y;
    acc.z += p * vb.x; acc.w += p * vb.y;
}

__global__ void edge_attn1(const unsigned* __restrict__ q,
                           const uint4* __restrict__ kvp,
                           const float* __restrict__ skip,
                           float* __restrict__ h, int n)
{
    int warp = (blockIdx.x * blockDim.x + threadIdx.x) >> 5;
    int lane = threadIdx.x & 31;
    if (warp >= n) return;
    int node = warp;

    uint2 qu = ((const uint2*)q)[(size_t)node * 32 + lane];
    float2 q01 = unpack_bf2(qu.x), q23 = unpack_bf2(qu.y);

    float4 acc = make_float4(0.f, 0.f, 0.f, 0.f);
    float den = 0.f;
    int beg = g_rowptr[node], end = g_rowptr[node + 1];

    int e = beg;
    int s0 = 0, s1 = 0, s2 = 0, s3 = 0;
    if (e + 3 < end) {
        s0 = g_csr_src[e];     s1 = g_csr_src[e + 1];
        s2 = g_csr_src[e + 2]; s3 = g_csr_src[e + 3];
    }
    for (; e + 3 < end; e += 4) {
        int n0 = s0, n1 = s1, n2 = s2, n3 = s3;
        if (e + 7 < end) {
            n0 = g_csr_src[e + 4]; n1 = g_csr_src[e + 5];
            n2 = g_csr_src[e + 6]; n3 = g_csr_src[e + 7];
        }
        uint4 kv0 = ld_kv(&kvp[(size_t)s0 * 32 + lane]);
        uint4 kv1 = ld_kv(&kvp[(size_t)s1 * 32 + lane]);
        uint4 kv2 = ld_kv(&kvp[(size_t)s2 * 32 + lane]);
        uint4 kv3 = ld_kv(&kvp[(size_t)s3 * 32 + lane]);
        float2 ka0 = unpack_bf2(kv0.x), kb0 = unpack_bf2(kv0.y);
        float2 ka1 = unpack_bf2(kv1.x), kb1 = unpack_bf2(kv1.y);
        float2 ka2 = unpack_bf2(kv2.x), kb2 = unpack_bf2(kv2.y);
        float2 ka3 = unpack_bf2(kv3.x), kb3 = unpack_bf2(kv3.y);
        float d0 = q01.x * ka0.x + q01.y * ka0.y + q23.x * kb0.x + q23.y * kb0.y;
        float d1 = q01.x * ka1.x + q01.y * ka1.y + q23.x * kb1.x + q23.y * kb1.y;
        float d2 = q01.x * ka2.x + q01.y * ka2.y + q23.x * kb2.x + q23.y * kb2.y;
        float d3 = q01.x * ka3.x + q01.y * ka3.y + q23.x * kb3.x + q23.y * kb3.y;
        d0 += __shfl_xor_sync(0xffffffffu, d0, 1);
        d1 += __shfl_xor_sync(0xffffffffu, d1, 1);
        d2 += __shfl_xor_sync(0xffffffffu, d2, 1);
        d3 += __shfl_xor_sync(0xffffffffu, d3, 1);
        d0 += __shfl_xor_sync(0xffffffffu, d0, 2);
        d1 += __shfl_xor_sync(0xffffffffu, d1, 2);
        d2 += __shfl_xor_sync(0xffffffffu, d2, 2);
        d3 += __shfl_xor_sync(0xffffffffu, d3, 2);
        d0 += __shfl_xor_sync(0xffffffffu, d0, 4);
        d1 += __shfl_xor_sync(0xffffffffu, d1, 4);
        d2 += __shfl_xor_sync(0xffffffffu, d2, 4);
        d3 += __shfl_xor_sync(0xffffffffu, d3, 4);
        float p0 = __expf(d0 * 0.17677669529663689f);
        float p1 = __expf(d1 * 0.17677669529663689f);
        float p2 = __expf(d2 * 0.17677669529663689f);
        float p3 = __expf(d3 * 0.17677669529663689f);
        den += (p0 + p1) + (p2 + p3);
        float2 va0 = unpack_bf2(kv0.z), vb0 = unpack_bf2(kv0.w);
        float2 va1 = unpack_bf2(kv1.z), vb1 = unpack_bf2(kv1.w);
        float2 va2 = unpack_bf2(kv2.z), vb2 = unpack_bf2(kv2.w);
        float2 va3 = unpack_bf2(kv3.z), vb3 = unpack_bf2(kv3.w);
        acc.x += (p0 * va0.x + p1 * va1.x) + (p2 * va2.x + p3 * va3.x);
        acc.y += (p0 * va0.y + p1 * va1.y) + (p2 * va2.y + p3 * va3.y);
        acc.z += (p0 * vb0.x + p1 * vb1.x) + (p2 * vb2.x + p3 * vb3.x);
        acc.w += (p0 * vb0.y + p1 * vb1.y) + (p2 * vb2.y + p3 * vb3.y);
        s0 = n0; s1 = n1; s2 = n2; s3 = n3;
    }
    for (; e < end; e++)
        attn1_edge(kvp, g_csr_src[e], lane, q01, q23, acc, den);

    float inv = (den > 0.f) ? (1.f / den) : 0.f;
    float4 sk = *(const float4*)&skip[(size_t)node * 128 + lane * 4];
    float4 o = make_float4(fmaxf(sk.x + acc.x * inv, 0.f),
                           fmaxf(sk.y + acc.y * inv, 0.f),
                           fmaxf(sk.z + acc.z * inv, 0.f),
                           fmaxf(sk.w + acc.w * inv, 0.f));
    *(float4*)&h[(size_t)node * 128 + lane * 4] = o;
}

// ---------------- fused edge attention + partial colsum, layer 2 ----------
__global__ void edge_attn2(const unsigned* __restrict__ q,
                           const uint4* __restrict__ kvp,
                           const float* __restrict__ skip,
                           float* __restrict__ part, int n)
{
    __shared__ float cs[32];
    int tid = blockIdx.x * blockDim.x + threadIdx.x;
    int node = tid >> 3;
    int m = threadIdx.x & 7;
    unsigned gmask = 0xFFu << ((threadIdx.x & 31) & ~7);
    bool valid = node < n;

    float2 q01 = make_float2(0.f, 0.f), q23 = make_float2(0.f, 0.f);
    int beg = 0, end = 0;
    if (valid) {
        uint2 qu = ((const uint2*)q)[(size_t)node * 8 + m];
        q01 = unpack_bf2(qu.x); q23 = unpack_bf2(qu.y);
        beg = g_rowptr[node]; end = g_rowptr[node + 1];
    }

    float4 acc = make_float4(0.f, 0.f, 0.f, 0.f);
    float den = 0.f;
    int e = beg;
    for (; e + 3 < end; e += 4) {
        int s0 = g_csr_src[e],     s1 = g_csr_src[e + 1];
        int s2 = g_csr_src[e + 2], s3 = g_csr_src[e + 3];
        uint4 kv0 = ld_kv(&kvp[(size_t)s0 * 8 + m]);
        uint4 kv1 = ld_kv(&kvp[(size_t)s1 * 8 + m]);
        uint4 kv2 = ld_kv(&kvp[(size_t)s2 * 8 + m]);
        uint4 kv3 = ld_kv(&kvp[(size_t)s3 * 8 + m]);
        float2 ka0 = unpack_bf2(kv0.x), kb0 = unpack_bf2(kv0.y);
        float2 ka1 = unpack_bf2(kv1.x), kb1 = unpack_bf2(kv1.y);
        float2 ka2 = unpack_bf2(kv2.x), kb2 = unpack_bf2(kv2.y);
        float2 ka3 = unpack_bf2(kv3.x), kb3 = unpack_bf2(kv3.y);
        float d0 = q01.x * ka0.x + q01.y * ka0.y + q23.x * kb0.x + q23.y * kb0.y;
        float d1 = q01.x * ka1.x + q01.y * ka1.y + q23.x * kb1.x + q23.y * kb1.y;
        float d2 = q01.x * ka2.x + q01.y * ka2.y + q23.x * kb2.x + q23.y * kb2.y;
        float d3 = q01.x * ka3.x + q01.y * ka3.y + q23.x * kb3.x + q23.y * kb3.y;
        d0 += __shfl_xor_sync(gmask, d0, 1);
        d1 += __shfl_xor_sync(gmask, d1, 1);
        d2 += __shfl_xor_sync(gmask, d2, 1);
        d3 += __shfl_xor_sync(gmask, d3, 1);
        d0 += __shfl_xor_sync(gmask, d0, 2);
        d1 += __shfl_xor_sync(gmask, d1, 2);
        d2 += __shfl_xor_sync(gmask, d2, 2);
        d3 += __shfl_xor_sync(gmask, d3, 2);
        d0 += __shfl_xor_sync(gmask, d0, 4);
        d1 += __shfl_xor_sync(gmask, d1, 4);
        d2 += __shfl_xor_sync(gmask, d2, 4);
        d3 += __shfl_xor_sync(gmask, d3, 4);
        float p0 = __expf(d0 * 0.17677669529663689f);
        float p1 = __expf(d1 * 0.17677669529663689f);
        float p2 = __expf(d2 * 0.17677669529663689f);
        float p3 = __expf(d3 * 0.17677669529663689f);
        den += (p0 + p1) + (p2 + p3);
        float2 va0 = unpack_bf2(kv0.z), vb0 = unpack_bf2(kv0.w);
        float2 va1 = unpack_bf2(kv1.z), vb1 = unpack_bf2(kv1.w);
        float2 va2 = unpack_bf2(kv2.z), vb2 = unpack_bf2(kv2.w);
        float2 va3 = unpack_bf2(kv3.z), vb3 = unpack_bf2(kv3.w);
        acc.x += (p0 * va0.x + p1 * va1.x) + (p2 * va2.x + p3 * va3.x);
        acc.y += (p0 * va0.y + p1 * va1.y) + (p2 * va2.y + p3 * va3.y);
        acc.z += (p0 * vb0.x + p1 * vb1.x) + (p2 * vb2.x + p3 * vb3.x);
        acc.w += (p0 * vb0.y + p1 * vb1.y) + (p2 * vb2.y + p3 * vb3.y);
    }
    for (; e < end; e++) {
        int s0 = g_csr_src[e];
        uint4 kv0 = ld_kv(&kvp[(size_t)s0 * 8 + m]);
        float2 ka0 = unpack_bf2(kv0.x), kb0 = unpack_bf2(kv0.y);
        float d0 = q01.x * ka0.x + q01.y * ka0.y + q23.x * kb0.x + q23.y * kb0.y;
        d0 += __shfl_xor_sync(gmask, d0, 1);
        d0 += __shfl_xor_sync(gmask, d0, 2);
        d0 += __shfl_xor_sync(gmask, d0, 4);
        float p0 = __expf(d0 * 0.17677669529663689f);
        den += p0;
        float2 va0 = unpack_bf2(kv0.z), vb0 = unpack_bf2(kv0.w);
        acc.x += p0 * va0.x; acc.y += p0 * va0.y;
        acc.z += p0 * vb0.x; acc.w += p0 * vb0.y;
    }

    float o0 = 0.f, o1 = 0.f, o2 = 0.f, o3 = 0.f;
    if (valid) {
        float inv = (den > 0.f) ? (1.f / den) : 0.f;
        float4 sk = *(const float4*)&skip[(size_t)node * 32 + m * 4];
        o0 = fmaxf(sk.x + acc.x * inv, 0.f);
        o1 = fmaxf(sk.y + acc.y * inv, 0.f);
        o2 = fmaxf(sk.z + acc.z * inv, 0.f);
        o3 = fmaxf(sk.w + acc.w * inv, 0.f);
    }

    o0 += __shfl_xor_sync(0xffffffffu, o0, 8);
    o1 += __shfl_xor_sync(0xffffffffu, o1, 8);
    o2 += __shfl_xor_sync(0xffffffffu, o2, 8);
    o3 += __shfl_xor_sync(0xffffffffu, o3, 8);
    o0 += __shfl_xor_sync(0xffffffffu, o0, 16);
    o1 += __shfl_xor_sync(0xffffffffu, o1, 16);
    o2 += __shfl_xor_sync(0xffffffffu, o2, 16);
    o3 += __shfl_xor_sync(0xffffffffu, o3, 16);

    if (threadIdx.x < 32) cs[threadIdx.x] = 0.f;
    __syncthreads();
    if ((threadIdx.x & 31) < 8) {
        atomicAdd(&cs[m * 4 + 0], o0);
        atomicAdd(&cs[m * 4 + 1], o1);
        atomicAdd(&cs[m * 4 + 2], o2);
        atomicAdd(&cs[m * 4 + 3], o3);
    }
    __syncthreads();
    if (threadIdx.x < 32) part[(size_t)blockIdx.x * 32 + threadIdx.x] = cs[threadIdx.x];
}

// ---------------- final: reduce partials, dot with Wo ----------------
__global__ void final_kernel(const float* __restrict__ Wo,
                             const float* __restrict__ bo,
                             float* __restrict__ out, int n, int nb2) {
    __shared__ float cs[32];
    int t = threadIdx.x;
    if (t < 32) cs[t] = 0.f;
    __syncthreads();
    int dim = t & 31, rs = t >> 5;
    float acc = 0.f;
    for (int r = rs; r < nb2; r += 32)
        acc += g_part[(size_t)r * 32 + dim];
    atomicAdd(&cs[dim], acc);
    __syncthreads();
    if (t < 32) {
        float val = (cs[t] / (float)n) * Wo[t];
        #pragma unroll
        for (int o = 16; o; o >>= 1) val += __shfl_down_sync(0xffffffffu, val, o);
        if (t == 0) out[0] = val + bo[0];
    }
}

// ---------------- launch ----------------
extern "C" void kernel_launch(void* const* d_in, const int* in_sizes, int n_in,
                              void* d_out, int out_size) {
    const float* x   = (const float*)d_in[0];
    const void*  ei  = d_in[1];
    const float* Wq1 = (const float*)d_in[2];  const float* bq1 = (const float*)d_in[3];
    const float* Wk1 = (const float*)d_in[4];  const float* bk1 = (const float*)d_in[5];
    const float* Wv1 = (const float*)d_in[6];  const float* bv1 = (const float*)d_in[7];
    const float* Ws1 = (const float*)d_in[8];  const float* bs1 = (const float*)d_in[9];
    const float* Wq2 = (const float*)d_in[10]; const float* bq2 = (const float*)d_in[11];
    const float* Wk2 = (const float*)d_in[12]; const float* bk2 = (const float*)d_in[13];
    const float* Wv2 = (const float*)d_in[14]; const float* bv2 = (const float*)d_in[15];
    const float* Ws2 = (const float*)d_in[16]; const float* bs2 = (const float*)d_in[17];
    const float* Wo  = (const float*)d_in[18]; const float* bo  = (const float*)d_in[19];
    float* out = (float*)d_out;

    int n = in_sizes[0] / 128;
    int E = in_sizes[1] / 2;
    if (n > MAX_NODES) n = MAX_NODES;
    if (E > MAX_EDGES) E = MAX_EDGES;

    unsigned *q1b, *q2b;
    uint4 *kv1, *kv2;
    float *s1, *h1, *s2, *part;
    cudaGetSymbolAddress((void**)&q1b, g_q1b);
    cudaGetSymbolAddress((void**)&kv1, g_kv1);
    cudaGetSymbolAddress((void**)&s1,  g_s1);
    cudaGetSymbolAddress((void**)&h1,  g_h1);
    cudaGetSymbolAddress((void**)&q2b, g_q2b);
    cudaGetSymbolAddress((void**)&kv2, g_kv2);
    cudaGetSymbolAddress((void**)&s2,  g_s2);
    cudaGetSymbolAddress((void**)&part, g_part);

    const int SMEM = 64 * SA * 4 + 2 * CHUNK_B;   // 67584 B
    cudaFuncSetAttribute(gemm_l1, cudaFuncAttributeMaxDynamicSharedMemorySize, SMEM);
    cudaFuncSetAttribute(gemm_l2, cudaFuncAttributeMaxDynamicSharedMemorySize, SMEM);

    int nb = (n + 2047) / 2048;
    int gb = (n + 63) / 64;
    int nb2 = (n + 31) / 32;

    // fork: preprocessing (edge-index work) on side stream, GEMM path on main
    static cudaStream_t sside = nullptr;
    static cudaEvent_t evFork = nullptr, evJoin = nullptr;
    if (!sside) {
        cudaStreamCreateWithFlags(&sside, cudaStreamNonBlocking);
        cudaEventCreateWithFlags(&evFork, cudaEventDisableTiming);
        cudaEventCreateWithFlags(&evJoin, cudaEventDisableTiming);
    }

    cudaEventRecord(evFork, 0);
    cudaStreamWaitEvent(sside, evFork, 0);

    // main: prepack1 + gemm_l1 (prepack2 deferred to after gemm_l1)
    prepack1<<<(4 * 4 * 16 * 128 + 255) / 256, 256>>>(Wq1, Wk1, Wv1, Ws1);
    init_kernel<<<(n + 256) / 256, 256, 0, sside>>>((const int*)ei, n);
    hist_kernel<<<(E + 255) / 256, 256, 0, sside>>>(ei, E);
    gemm_l1<<<dim3(gb, 4), 256, SMEM>>>(x, bq1, bk1, bv1, bs1,
                                        q1b, (unsigned*)kv1, s1, n);   // launch #4
    prepack2<<<(4 * 16 * 128 + 255) / 256, 256>>>(Wq2, Wk2, Wv2, Ws2);
    // side: rest of preprocessing
    scan_phase1<<<nb, 256, 0, sside>>>(n);
    scan_phase3<<<(n + 255) / 256, 256, 0, sside>>>(n, nb);
    fill_kernel<<<(E + 255) / 256, 256, 0, sside>>>(ei, E);
    cudaEventRecord(evJoin, sside);

    cudaStreamWaitEvent(0, evJoin, 0);   // join before attention

    edge_attn1<<<(n * 32 + 255) / 256, 256>>>(q1b, kv1, s1, h1, n);
    gemm_l2<<<gb, 256, SMEM>>>(h1, bq2, bk2, bv2, bs2,
                               q2b, (unsigned*)kv2, s2, n);
    edge_attn2<<<nb2, 256>>>(q2b, kv2, s2, part, n);
    final_kernel<<<1, 1024>>>(Wo, bo, out, n, nb2);
}

// round 17
// speedup vs baseline: 1.0163x; 1.0163x over previous
#include <cuda_runtime.h>
#include <cuda_bf16.h>
#include <cstdint>

#define MAX_NODES 50000
#define MAX_EDGES 800000
#define SA 132            // As row stride (floats)
#define WROW 132          // packed-W row stride (float2)
#define CHUNK_F2 (16 * WROW)        // float2 per 32-k-row chunk = 2112
#define CHUNK_B  (CHUNK_F2 * 8)     // bytes per chunk = 16896
#define CHUNK_16 (CHUNK_B / 16)     // 16B copies per chunk = 1056

// ---------------- device scratch ----------------
__device__ int   g_is64;
__device__ int   g_deg[MAX_NODES + 1];
__device__ int   g_rowptr[MAX_NODES + 1];
__device__ int   g_cursor[MAX_NODES];
__device__ int   g_csr_src[MAX_EDGES];
__device__ int   g_bsum[64];

// pre-packed tf32 weights (float2 pairs matching mma B fragment)
__device__ __align__(16) float2 g_wp1[16 * CHUNK_F2];   // 4 W x 4 chunks
__device__ __align__(16) float2 g_wp2[4 * CHUNK_F2];    // concat W, 4 chunks

// layer 1: q packed bf16; k/v interleaved per-lane {k0,k1,v0,v1}; skip/h1 fp32
__device__ __align__(16) unsigned g_q1b[MAX_NODES * 64];
__device__ uint4    g_kv1[MAX_NODES * 32];
__device__ float    g_s1[MAX_NODES * 128];
__device__ float    g_h1[MAX_NODES * 128];

// layer 2
__device__ __align__(16) unsigned g_q2b[MAX_NODES * 16];
__device__ uint4    g_kv2[MAX_NODES * 8];
__device__ float    g_s2[MAX_NODES * 32];

__device__ float g_part[((MAX_NODES + 31) / 32) * 32];

// ---------------- helpers ----------------
__device__ __forceinline__ unsigned pack_bf2(float a, float b) {
    __nv_bfloat162 h = __floats2bfloat162_rn(a, b);
    return *(unsigned*)&h;
}
__device__ __forceinline__ float2 unpack_bf2(unsigned u) {
    __nv_bfloat162 h = *(__nv_bfloat162*)&u;
    return __bfloat1622float2(h);
}
__device__ __forceinline__ float f2tf(float f) {
    unsigned u;
    asm("cvt.rna.tf32.f32 %0, %1;" : "=r"(u) : "f"(f));
    return __uint_as_float(u);
}
__device__ __forceinline__ void mma_tf32(float* c, const unsigned* a, const unsigned* b) {
    asm volatile("mma.sync.aligned.m16n8k8.row.col.f32.tf32.tf32.f32 "
                 "{%0,%1,%2,%3}, {%4,%5,%6,%7}, {%8,%9}, {%0,%1,%2,%3};"
                 : "+f"(c[0]), "+f"(c[1]), "+f"(c[2]), "+f"(c[3])
                 : "r"(a[0]), "r"(a[1]), "r"(a[2]), "r"(a[3]), "r"(b[0]), "r"(b[1]));
}
__device__ __forceinline__ void cp16(void* smem, const void* gmem) {
    unsigned sa = (unsigned)__cvta_generic_to_shared(smem);
    asm volatile("cp.async.cg.shared.global [%0], [%1], 16;" :: "r"(sa), "l"(gmem));
}
#define CP_COMMIT() asm volatile("cp.async.commit_group;")
#define CP_WAIT0()  asm volatile("cp.async.wait_group 0;")

// ---------------- weight pre-pack ----------------
__global__ void prepack1(const float* __restrict__ W0, const float* __restrict__ W1,
                         const float* __restrict__ W2, const float* __restrict__ W3) {
    int i = blockIdx.x * blockDim.x + threadIdx.x;      // 4*4*16*128
    if (i >= 4 * 4 * 16 * 128) return;
    int col = i & 127, r16 = (i >> 7) & 15, ch = (i >> 11) & 3, w = i >> 13;
    int kk = r16 >> 2, tig = r16 & 3;
    int kr = ch * 32 + kk * 8 + tig;
    const float* Wl[4] = {W0, W1, W2, W3};
    const float* W = Wl[w];
    g_wp1[((w * 4 + ch) * 16 + r16) * WROW + col] =
        make_float2(f2tf(W[(size_t)kr * 128 + col]), f2tf(W[(size_t)(kr + 4) * 128 + col]));
}

__global__ void prepack2(const float* __restrict__ W0, const float* __restrict__ W1,
                         const float* __restrict__ W2, const float* __restrict__ W3) {
    int i = blockIdx.x * blockDim.x + threadIdx.x;      // 4*16*128
    if (i >= 4 * 16 * 128) return;
    int col = i & 127, r16 = (i >> 7) & 15, ch = i >> 11;
    int kk = r16 >> 2, tig = r16 & 3;
    int kr = ch * 32 + kk * 8 + tig;
    const float* Wl[4] = {W0, W1, W2, W3};
    int mat = col >> 5, lc = col & 31;
    const float* W = Wl[mat];
    g_wp2[(ch * 16 + r16) * WROW + col] =
        make_float2(f2tf(W[(size_t)kr * 32 + lc]), f2tf(W[(size_t)(kr + 4) * 32 + lc]));
}

// ---------------- preprocessing ----------------
__global__ void init_kernel(const int* __restrict__ ei, int n) {
    int i = blockIdx.x * blockDim.x + threadIdx.x;
    if (i == 0) {
        int all_zero_hi = 1;
        for (int j = 0; j < 64; j++)
            if (ei[2 * j + 1] != 0) all_zero_hi = 0;
        g_is64 = all_zero_hi;
    }
    if (i <= n) g_deg[i] = 0;
}

__global__ void hist_kernel(const void* __restrict__ ei, int E) {
    int e = blockIdx.x * blockDim.x + threadIdx.x;
    if (e >= E) return;
    int d;
    if (g_is64) d = (int)((const long long*)ei)[E + e];
    else        d = ((const int*)ei)[E + e];
    atomicAdd(&g_deg[d], 1);
}

__global__ void scan_phase1(int n) {
    __shared__ int wsum[8];
    __shared__ int woff[8];
    int t = threadIdx.x, lane = t & 31, warp = t >> 5;
    int base = blockIdx.x * 2048 + t * 8;
    int v[8], s = 0;
    #pragma unroll
    for (int i = 0; i < 8; i++) {
        int idx = base + i;
        int x = (idx < n) ? g_deg[idx] : 0;
        v[i] = s;
        s += x;
    }
    int x = s;
    #pragma unroll
    for (int o = 1; o < 32; o <<= 1) {
        int y = __shfl_up_sync(0xffffffffu, x, o);
        if (lane >= o) x += y;
    }
    if (lane == 31) wsum[warp] = x;
    __syncthreads();
    if (t == 0) {
        int run = 0;
        #pragma unroll
        for (int j = 0; j < 8; j++) { int tmp = wsum[j]; woff[j] = run; run += tmp; }
        g_bsum[blockIdx.x] = run;
    }
    __syncthreads();
    int off = woff[warp] + (x - s);
    #pragma unroll
    for (int i = 0; i < 8; i++) {
        int idx = base + i;
        if (idx < n) g_rowptr[idx] = off + v[i];
    }
}

__global__ void scan_phase3(int n, int nb) {
    __shared__ int boff[33];
    int t = threadIdx.x;
    if (t < 32) {
        int v = (t < nb) ? g_bsum[t] : 0;
        int x = v;
        #pragma unroll
        for (int o = 1; o < 32; o <<= 1) {
            int y = __shfl_up_sync(0xffffffffu, x, o);
            if (t >= o) x += y;
        }
        boff[t] = x - v;
        if (t == 31) boff[32] = x;
    }
    __syncthreads();
    int idx = blockIdx.x * blockDim.x + t;
    if (idx < n) {
        int val = g_rowptr[idx] + boff[idx >> 11];
        g_rowptr[idx] = val;
        g_cursor[idx] = val;
    }
    if (idx == 0) g_rowptr[n] = boff[32];
}

__global__ void fill_kernel(const void* __restrict__ ei, int E) {
    int e = blockIdx.x * blockDim.x + threadIdx.x;
    if (e >= E) return;
    int s, d;
    if (g_is64) {
        const long long* p = (const long long*)ei;
        s = (int)p[e];
        d = (int)p[E + e];
    } else {
        const int* p = (const int*)ei;
        s = p[e];
        d = p[E + e];
    }
    int pos = atomicAdd(&g_cursor[d], 1);
    g_csr_src[pos] = s;
}

// ---------------- mma on one 32-k-row chunk; warp tile 32(m) x 32(n) ------
__device__ __forceinline__ void mma_chunk(const float* As, const float2* Wc,
                                          int kbase, int warp_m, int warp_n,
                                          int lane, float c[2][4][4]) {
    int gid = lane >> 2, tig = lane & 3;
    const float* ab = &As[(warp_m * 32 + gid) * SA];
    #pragma unroll
    for (int kk = 0; kk < 4; kk++) {
        int kc0 = kbase + kk * 8 + tig;
        unsigned a0[4], a1[4];
        a0[0] = __float_as_uint(ab[kc0]);
        a0[1] = __float_as_uint(ab[8 * SA + kc0]);
        a0[2] = __float_as_uint(ab[kc0 + 4]);
        a0[3] = __float_as_uint(ab[8 * SA + kc0 + 4]);
        a1[0] = __float_as_uint(ab[16 * SA + kc0]);
        a1[1] = __float_as_uint(ab[24 * SA + kc0]);
        a1[2] = __float_as_uint(ab[16 * SA + kc0 + 4]);
        a1[3] = __float_as_uint(ab[24 * SA + kc0 + 4]);
        const float2* wrow = &Wc[(kk * 4 + tig) * WROW + warp_n * 32 + gid];
        #pragma unroll
        for (int nt = 0; nt < 4; nt++) {
            float2 bv = wrow[nt * 8];
            unsigned b[2] = {__float_as_uint(bv.x), __float_as_uint(bv.y)};
            mma_tf32(c[0][nt], a0, b);
            mma_tf32(c[1][nt], a1, b);
        }
    }
}

__device__ __forceinline__ void stage_chunk(const float2* __restrict__ src, float2* dst, int t) {
    const char* s = (const char*)src;
    char* d = (char*)dst;
    #pragma unroll
    for (int i = t; i < CHUNK_16; i += 256)
        cp16(d + i * 16, s + i * 16);
    CP_COMMIT();
}

// ---------------- GEMM layer 1: BM=64, w = blockIdx.y ----------------------
__global__ __launch_bounds__(256, 3) void gemm_l1(
    const float* __restrict__ A,
    const float* __restrict__ b0, const float* __restrict__ b1,
    const float* __restrict__ b2, const float* __restrict__ b3,
    unsigned* __restrict__ oq, unsigned* __restrict__ kv,
    float* __restrict__ os, int M)
{
    extern __shared__ float smf[];
    float* As = smf;                               // 64 x SA
    float2* Wb = (float2*)(smf + 64 * SA);         // 2 x CHUNK_F2

    int t = threadIdx.x, lane = t & 31, wid = t >> 5;
    int warp_m = wid & 1, warp_n = wid >> 1;
    int row0 = blockIdx.x * 64;
    int w = blockIdx.y;

    stage_chunk(g_wp1 + (w * 4) * CHUNK_F2, Wb, t);   // chunk 0 -> buf 0

    for (int i = t; i < 64 * 32; i += 256) {
        int r = i >> 5, c4 = i & 31;
        float4 v = make_float4(0.f, 0.f, 0.f, 0.f);
        if (row0 + r < M) v = *(const float4*)&A[(size_t)(row0 + r) * 128 + c4 * 4];
        *(float4*)&As[r * SA + c4 * 4] =
            make_float4(f2tf(v.x), f2tf(v.y), f2tf(v.z), f2tf(v.w));
    }

    const float* bl[4] = {b0, b1, b2, b3};

    float c[2][4][4];
    #pragma unroll
    for (int i = 0; i < 2; i++)
        #pragma unroll
        for (int j = 0; j < 4; j++)
            #pragma unroll
            for (int q = 0; q < 4; q++) c[i][j][q] = 0.f;

    #pragma unroll
    for (int kc = 0; kc < 4; kc++) {
        CP_WAIT0();
        __syncthreads();
        if (kc < 3)
            stage_chunk(g_wp1 + (w * 4 + kc + 1) * CHUNK_F2,
                        Wb + ((kc + 1) & 1) * CHUNK_F2, t);
        mma_chunk(As, Wb + (kc & 1) * CHUNK_F2, kc * 32, warp_m, warp_n, lane, c);
    }

    #pragma unroll
    for (int mt = 0; mt < 2; mt++) {
        #pragma unroll
        for (int nt = 0; nt < 4; nt++) {
            int rg = row0 + warp_m * 32 + mt * 16 + (lane >> 2);
            int col = warp_n * 32 + nt * 8 + (lane & 3) * 2;
            int u = col >> 1;
            float2 bb = *(const float2*)&bl[w][col];
            float x0 = c[mt][nt][0] + bb.x, x1 = c[mt][nt][1] + bb.y;
            float x2 = c[mt][nt][2] + bb.x, x3 = c[mt][nt][3] + bb.y;
            if (w == 0) {
                if (rg < M)     oq[(size_t)rg * 64 + u] = pack_bf2(x0, x1);
                if (rg + 8 < M) oq[(size_t)(rg + 8) * 64 + u] = pack_bf2(x2, x3);
            } else if (w < 3) {
                int off = (u >> 1) * 4 + (u & 1) + ((w == 1) ? 0 : 2);
                if (rg < M)     kv[(size_t)rg * 128 + off] = pack_bf2(x0, x1);
                if (rg + 8 < M) kv[(size_t)(rg + 8) * 128 + off] = pack_bf2(x2, x3);
            } else {
                if (rg < M)     *(float2*)&os[(size_t)rg * 128 + col] = make_float2(x0, x1);
                if (rg + 8 < M) *(float2*)&os[(size_t)(rg + 8) * 128 + col] = make_float2(x2, x3);
            }
        }
    }
}

// ---------------- GEMM layer 2: BM=64, K=128, concat W ---------------------
__global__ __launch_bounds__(256, 3) void gemm_l2(
    const float* __restrict__ A,
    const float* __restrict__ b0, const float* __restrict__ b1,
    const float* __restrict__ b2, const float* __restrict__ b3,
    unsigned* __restrict__ oq, unsigned* __restrict__ kv,
    float* __restrict__ os, int M)
{
    extern __shared__ float smf[];
    float* As = smf;
    float2* Wb = (float2*)(smf + 64 * SA);

    int t = threadIdx.x, lane = t & 31, wid = t >> 5;
    int warp_m = wid & 1, warp_n = wid >> 1;
    int row0 = blockIdx.x * 64;

    stage_chunk(g_wp2, Wb, t);

    for (int i = t; i < 64 * 32; i += 256) {
        int r = i >> 5, c4 = i & 31;
        float4 v = make_float4(0.f, 0.f, 0.f, 0.f);
        if (row0 + r < M) v = *(const float4*)&A[(size_t)(row0 + r) * 128 + c4 * 4];
        *(float4*)&As[r * SA + c4 * 4] =
            make_float4(f2tf(v.x), f2tf(v.y), f2tf(v.z), f2tf(v.w));
    }

    const float* bl[4] = {b0, b1, b2, b3};

    float c[2][4][4];
    #pragma unroll
    for (int i = 0; i < 2; i++)
        #pragma unroll
        for (int j = 0; j < 4; j++)
            #pragma unroll
            for (int q = 0; q < 4; q++) c[i][j][q] = 0.f;

    #pragma unroll
    for (int ch = 0; ch < 4; ch++) {
        CP_WAIT0();
        __syncthreads();
        if (ch < 3)
            stage_chunk(g_wp2 + (ch + 1) * CHUNK_F2, Wb + ((ch + 1) & 1) * CHUNK_F2, t);
        mma_chunk(As, Wb + (ch & 1) * CHUNK_F2, ch * 32, warp_m, warp_n, lane, c);
    }

    // mat == warp_n (each 32-col group is one matrix)
    #pragma unroll
    for (int mt = 0; mt < 2; mt++) {
        #pragma unroll
        for (int nt = 0; nt < 4; nt++) {
            int rg = row0 + warp_m * 32 + mt * 16 + (lane >> 2);
            int lc = nt * 8 + (lane & 3) * 2;
            int u = lc >> 1;
            float2 bb = *(const float2*)&bl[warp_n][lc];
            float x0 = c[mt][nt][0] + bb.x, x1 = c[mt][nt][1] + bb.y;
            float x2 = c[mt][nt][2] + bb.x, x3 = c[mt][nt][3] + bb.y;
            if (warp_n == 0) {
                if (rg < M)     oq[(size_t)rg * 16 + u] = pack_bf2(x0, x1);
                if (rg + 8 < M) oq[(size_t)(rg + 8) * 16 + u] = pack_bf2(x2, x3);
            } else if (warp_n < 3) {
                int off = (u >> 1) * 4 + (u & 1) + ((warp_n == 1) ? 0 : 2);
                if (rg < M)     kv[(size_t)rg * 32 + off] = pack_bf2(x0, x1);
                if (rg + 8 < M) kv[(size_t)(rg + 8) * 32 + off] = pack_bf2(x2, x3);
            } else {
                if (rg < M)     *(float2*)&os[(size_t)rg * 32 + lc] = make_float2(x0, x1);
                if (rg + 8 < M) *(float2*)&os[(size_t)(rg + 8) * 32 + lc] = make_float2(x2, x3);
            }
        }
    }
}

// ---------------- fused edge attention, layer 1 (4 heads x 32) -------------
// x4 unroll with pipelined index prefetch
__device__ __forceinline__ void attn1_edge(const uint4* kvp, int s, int lane,
                                           float2 q01, float2 q23,
                                           float4& acc, float& den) {
    uint4 kv0 = kvp[(size_t)s * 32 + lane];
    float2 ka = unpack_bf2(kv0.x), kb = unpack_bf2(kv0.y);
    float d = q01.x * ka.x + q01.y * ka.y + q23.x * kb.x + q23.y * kb.y;
    d += __shfl_xor_sync(0xffffffffu, d, 1);
    d += __shfl_xor_sync(0xffffffffu, d, 2);
    d += __shfl_xor_sync(0xffffffffu, d, 4);
    float p = __expf(d * 0.17677669529663689f);
    den += p;
    float2 va = unpack_bf2(kv0.z), vb = unpack_bf2(kv0.w);
    acc.x += p * va.x; acc.y += p * va.y;
    acc.z += p * vb.x; acc.w += p * vb.y;
}

__global__ void edge_attn1(const unsigned* __restrict__ q,
                           const uint4* __restrict__ kvp,
                           const float* __restrict__ skip,
                           float* __restrict__ h, int n)
{
    int warp = (blockIdx.x * blockDim.x + threadIdx.x) >> 5;
    int lane = threadIdx.x & 31;
    if (warp >= n) return;
    int node = warp;

    uint2 qu = ((const uint2*)q)[(size_t)node * 32 + lane];
    float2 q01 = unpack_bf2(qu.x), q23 = unpack_bf2(qu.y);

    float4 acc = make_float4(0.f, 0.f, 0.f, 0.f);
    float den = 0.f;
    int beg = g_rowptr[node], end = g_rowptr[node + 1];

    int e = beg;
    int s0 = 0, s1 = 0, s2 = 0, s3 = 0;
    if (e + 3 < end) {
        s0 = g_csr_src[e];     s1 = g_csr_src[e + 1];
        s2 = g_csr_src[e + 2]; s3 = g_csr_src[e + 3];
    }
    for (; e + 3 < end; e += 4) {
        // prefetch indices for next batch while current kv loads fly
        int n0 = s0, n1 = s1, n2 = s2, n3 = s3;
        if (e + 7 < end) {
            n0 = g_csr_src[e + 4]; n1 = g_csr_src[e + 5];
            n2 = g_csr_src[e + 6]; n3 = g_csr_src[e + 7];
        }
        uint4 kv0 = kvp[(size_t)s0 * 32 + lane];
        uint4 kv1 = kvp[(size_t)s1 * 32 + lane];
        uint4 kv2 = kvp[(size_t)s2 * 32 + lane];
        uint4 kv3 = kvp[(size_t)s3 * 32 + lane];
        float2 ka0 = unpack_bf2(kv0.x), kb0 = unpack_bf2(kv0.y);
        float2 ka1 = unpack_bf2(kv1.x), kb1 = unpack_bf2(kv1.y);
        float2 ka2 = unpack_bf2(kv2.x), kb2 = unpack_bf2(kv2.y);
        float2 ka3 = unpack_bf2(kv3.x), kb3 = unpack_bf2(kv3.y);
        float d0 = q01.x * ka0.x + q01.y * ka0.y + q23.x * kb0.x + q23.y * kb0.y;
        float d1 = q01.x * ka1.x + q01.y * ka1.y + q23.x * kb1.x + q23.y * kb1.y;
        float d2 = q01.x * ka2.x + q01.y * ka2.y + q23.x * kb2.x + q23.y * kb2.y;
        float d3 = q01.x * ka3.x + q01.y * ka3.y + q23.x * kb3.x + q23.y * kb3.y;
        d0 += __shfl_xor_sync(0xffffffffu, d0, 1);
        d1 += __shfl_xor_sync(0xffffffffu, d1, 1);
        d2 += __shfl_xor_sync(0xffffffffu, d2, 1);
        d3 += __shfl_xor_sync(0xffffffffu, d3, 1);
        d0 += __shfl_xor_sync(0xffffffffu, d0, 2);
        d1 += __shfl_xor_sync(0xffffffffu, d1, 2);
        d2 += __shfl_xor_sync(0xffffffffu, d2, 2);
        d3 += __shfl_xor_sync(0xffffffffu, d3, 2);
        d0 += __shfl_xor_sync(0xffffffffu, d0, 4);
        d1 += __shfl_xor_sync(0xffffffffu, d1, 4);
        d2 += __shfl_xor_sync(0xffffffffu, d2, 4);
        d3 += __shfl_xor_sync(0xffffffffu, d3, 4);
        float p0 = __expf(d0 * 0.17677669529663689f);
        float p1 = __expf(d1 * 0.17677669529663689f);
        float p2 = __expf(d2 * 0.17677669529663689f);
        float p3 = __expf(d3 * 0.17677669529663689f);
        den += (p0 + p1) + (p2 + p3);
        float2 va0 = unpack_bf2(kv0.z), vb0 = unpack_bf2(kv0.w);
        float2 va1 = unpack_bf2(kv1.z), vb1 = unpack_bf2(kv1.w);
        float2 va2 = unpack_bf2(kv2.z), vb2 = unpack_bf2(kv2.w);
        float2 va3 = unpack_bf2(kv3.z), vb3 = unpack_bf2(kv3.w);
        acc.x += (p0 * va0.x + p1 * va1.x) + (p2 * va2.x + p3 * va3.x);
        acc.y += (p0 * va0.y + p1 * va1.y) + (p2 * va2.y + p3 * va3.y);
        acc.z += (p0 * vb0.x + p1 * vb1.x) + (p2 * vb2.x + p3 * vb3.x);
        acc.w += (p0 * vb0.y + p1 * vb1.y) + (p2 * vb2.y + p3 * vb3.y);
        s0 = n0; s1 = n1; s2 = n2; s3 = n3;
    }
    for (; e < end; e++)
        attn1_edge(kvp, g_csr_src[e], lane, q01, q23, acc, den);

    float inv = (den > 0.f) ? (1.f / den) : 0.f;
    float4 sk = *(const float4*)&skip[(size_t)node * 128 + lane * 4];
    float4 o = make_float4(fmaxf(sk.x + acc.x * inv, 0.f),
                           fmaxf(sk.y + acc.y * inv, 0.f),
                           fmaxf(sk.z + acc.z * inv, 0.f),
                           fmaxf(sk.w + acc.w * inv, 0.f));
    *(float4*)&h[(size_t)node * 128 + lane * 4] = o;
}

// ---------------- fused edge attention + partial colsum, layer 2 ----------
__global__ void edge_attn2(const unsigned* __restrict__ q,
                           const uint4* __restrict__ kvp,
                           const float* __restrict__ skip,
                           float* __restrict__ part, int n)
{
    __shared__ float cs[32];
    int tid = blockIdx.x * blockDim.x + threadIdx.x;
    int node = tid >> 3;
    int m = threadIdx.x & 7;
    unsigned gmask = 0xFFu << ((threadIdx.x & 31) & ~7);
    bool valid = node < n;

    float2 q01 = make_float2(0.f, 0.f), q23 = make_float2(0.f, 0.f);
    int beg = 0, end = 0;
    if (valid) {
        uint2 qu = ((const uint2*)q)[(size_t)node * 8 + m];
        q01 = unpack_bf2(qu.x); q23 = unpack_bf2(qu.y);
        beg = g_rowptr[node]; end = g_rowptr[node + 1];
    }

    float4 acc = make_float4(0.f, 0.f, 0.f, 0.f);
    float den = 0.f;
    int e = beg;
    for (; e + 3 < end; e += 4) {
        int s0 = g_csr_src[e],     s1 = g_csr_src[e + 1];
        int s2 = g_csr_src[e + 2], s3 = g_csr_src[e + 3];
        uint4 kv0 = kvp[(size_t)s0 * 8 + m];
        uint4 kv1 = kvp[(size_t)s1 * 8 + m];
        uint4 kv2 = kvp[(size_t)s2 * 8 + m];
        uint4 kv3 = kvp[(size_t)s3 * 8 + m];
        float2 ka0 = unpack_bf2(kv0.x), kb0 = unpack_bf2(kv0.y);
        float2 ka1 = unpack_bf2(kv1.x), kb1 = unpack_bf2(kv1.y);
        float2 ka2 = unpack_bf2(kv2.x), kb2 = unpack_bf2(kv2.y);
        float2 ka3 = unpack_bf2(kv3.x), kb3 = unpack_bf2(kv3.y);
        float d0 = q01.x * ka0.x + q01.y * ka0.y + q23.x * kb0.x + q23.y * kb0.y;
        float d1 = q01.x * ka1.x + q01.y * ka1.y + q23.x * kb1.x + q23.y * kb1.y;
        float d2 = q01.x * ka2.x + q01.y * ka2.y + q23.x * kb2.x + q23.y * kb2.y;
        float d3 = q01.x * ka3.x + q01.y * ka3.y + q23.x * kb3.x + q23.y * kb3.y;
        d0 += __shfl_xor_sync(gmask, d0, 1);
        d1 += __shfl_xor_sync(gmask, d1, 1);
        d2 += __shfl_xor_sync(gmask, d2, 1);
        d3 += __shfl_xor_sync(gmask, d3, 1);
        d0 += __shfl_xor_sync(gmask, d0, 2);
        d1 += __shfl_xor_sync(gmask, d1, 2);
        d2 += __shfl_xor_sync(gmask, d2, 2);
        d3 += __shfl_xor_sync(gmask, d3, 2);
        d0 += __shfl_xor_sync(gmask, d0, 4);
        d1 += __shfl_xor_sync(gmask, d1, 4);
        d2 += __shfl_xor_sync(gmask, d2, 4);
        d3 += __shfl_xor_sync(gmask, d3, 4);
        float p0 = __expf(d0 * 0.17677669529663689f);
        float p1 = __expf(d1 * 0.17677669529663689f);
        float p2 = __expf(d2 * 0.17677669529663689f);
        float p3 = __expf(d3 * 0.17677669529663689f);
        den += (p0 + p1) + (p2 + p3);
        float2 va0 = unpack_bf2(kv0.z), vb0 = unpack_bf2(kv0.w);
        float2 va1 = unpack_bf2(kv1.z), vb1 = unpack_bf2(kv1.w);
        float2 va2 = unpack_bf2(kv2.z), vb2 = unpack_bf2(kv2.w);
        float2 va3 = unpack_bf2(kv3.z), vb3 = unpack_bf2(kv3.w);
        acc.x += (p0 * va0.x + p1 * va1.x) + (p2 * va2.x + p3 * va3.x);
        acc.y += (p0 * va0.y + p1 * va1.y) + (p2 * va2.y + p3 * va3.y);
        acc.z += (p0 * vb0.x + p1 * vb1.x) + (p2 * vb2.x + p3 * vb3.x);
        acc.w += (p0 * vb0.y + p1 * vb1.y) + (p2 * vb2.y + p3 * vb3.y);
    }
    for (; e < end; e++) {
        int s0 = g_csr_src[e];
        uint4 kv0 = kvp[(size_t)s0 * 8 + m];
        float2 ka0 = unpack_bf2(kv0.x), kb0 = unpack_bf2(kv0.y);
        float d0 = q01.x * ka0.x + q01.y * ka0.y + q23.x * kb0.x + q23.y * kb0.y;
        d0 += __shfl_xor_sync(gmask, d0, 1);
        d0 += __shfl_xor_sync(gmask, d0, 2);
        d0 += __shfl_xor_sync(gmask, d0, 4);
        float p0 = __expf(d0 * 0.17677669529663689f);
        den += p0;
        float2 va0 = unpack_bf2(kv0.z), vb0 = unpack_bf2(kv0.w);
        acc.x += p0 * va0.x; acc.y += p0 * va0.y;
        acc.z += p0 * vb0.x; acc.w += p0 * vb0.y;
    }

    float o0 = 0.f, o1 = 0.f, o2 = 0.f, o3 = 0.f;
    if (valid) {
        float inv = (den > 0.f) ? (1.f / den) : 0.f;
        float4 sk = *(const float4*)&skip[(size_t)node * 32 + m * 4];
        o0 = fmaxf(sk.x + acc.x * inv, 0.f);
        o1 = fmaxf(sk.y + acc.y * inv, 0.f);
        o2 = fmaxf(sk.z + acc.z * inv, 0.f);
        o3 = fmaxf(sk.w + acc.w * inv, 0.f);
    }

    o0 += __shfl_xor_sync(0xffffffffu, o0, 8);
    o1 += __shfl_xor_sync(0xffffffffu, o1, 8);
    o2 += __shfl_xor_sync(0xffffffffu, o2, 8);
    o3 += __shfl_xor_sync(0xffffffffu, o3, 8);
    o0 += __shfl_xor_sync(0xffffffffu, o0, 16);
    o1 += __shfl_xor_sync(0xffffffffu, o1, 16);
    o2 += __shfl_xor_sync(0xffffffffu, o2, 16);
    o3 += __shfl_xor_sync(0xffffffffu, o3, 16);

    if (threadIdx.x < 32) cs[threadIdx.x] = 0.f;
    __syncthreads();
    if ((threadIdx.x & 31) < 8) {
        atomicAdd(&cs[m * 4 + 0], o0);
        atomicAdd(&cs[m * 4 + 1], o1);
        atomicAdd(&cs[m * 4 + 2], o2);
        atomicAdd(&cs[m * 4 + 3], o3);
    }
    __syncthreads();
    if (threadIdx.x < 32) part[(size_t)blockIdx.x * 32 + threadIdx.x] = cs[threadIdx.x];
}

// ---------------- final: reduce partials, dot with Wo ----------------
__global__ void final_kernel(const float* __restrict__ Wo,
                             const float* __restrict__ bo,
                             float* __restrict__ out, int n, int nb2) {
    __shared__ float cs[32];
    int t = threadIdx.x;
    if (t < 32) cs[t] = 0.f;
    __syncthreads();
    int dim = t & 31, rs = t >> 5;
    float acc = 0.f;
    for (int r = rs; r < nb2; r += 32)
        acc += g_part[(size_t)r * 32 + dim];
    atomicAdd(&cs[dim], acc);
    __syncthreads();
    if (t < 32) {
        float val = (cs[t] / (float)n) * Wo[t];
        #pragma unroll
        for (int o = 16; o; o >>= 1) val += __shfl_down_sync(0xffffffffu, val, o);
        if (t == 0) out[0] = val + bo[0];
    }
}

// ---------------- launch ----------------
extern "C" void kernel_launch(void* const* d_in, const int* in_sizes, int n_in,
                              void* d_out, int out_size) {
    const float* x   = (const float*)d_in[0];
    const void*  ei  = d_in[1];
    const float* Wq1 = (const float*)d_in[2];  const float* bq1 = (const float*)d_in[3];
    const float* Wk1 = (const float*)d_in[4];  const float* bk1 = (const float*)d_in[5];
    const float* Wv1 = (const float*)d_in[6];  const float* bv1 = (const float*)d_in[7];
    const float* Ws1 = (const float*)d_in[8];  const float* bs1 = (const float*)d_in[9];
    const float* Wq2 = (const float*)d_in[10]; const float* bq2 = (const float*)d_in[11];
    const float* Wk2 = (const float*)d_in[12]; const float* bk2 = (const float*)d_in[13];
    const float* Wv2 = (const float*)d_in[14]; const float* bv2 = (const float*)d_in[15];
    const float* Ws2 = (const float*)d_in[16]; const float* bs2 = (const float*)d_in[17];
    const float* Wo  = (const float*)d_in[18]; const float* bo  = (const float*)d_in[19];
    float* out = (float*)d_out;

    int n = in_sizes[0] / 128;
    int E = in_sizes[1] / 2;
    if (n > MAX_NODES) n = MAX_NODES;
    if (E > MAX_EDGES) E = MAX_EDGES;

    unsigned *q1b, *q2b;
    uint4 *kv1, *kv2;
    float *s1, *h1, *s2, *part;
    cudaGetSymbolAddress((void**)&q1b, g_q1b);
    cudaGetSymbolAddress((void**)&kv1, g_kv1);
    cudaGetSymbolAddress((void**)&s1,  g_s1);
    cudaGetSymbolAddress((void**)&h1,  g_h1);
    cudaGetSymbolAddress((void**)&q2b, g_q2b);
    cudaGetSymbolAddress((void**)&kv2, g_kv2);
    cudaGetSymbolAddress((void**)&s2,  g_s2);
    cudaGetSymbolAddress((void**)&part, g_part);

    const int SMEM = 64 * SA * 4 + 2 * CHUNK_B;   // 67584 B
    cudaFuncSetAttribute(gemm_l1, cudaFuncAttributeMaxDynamicSharedMemorySize, SMEM);
    cudaFuncSetAttribute(gemm_l2, cudaFuncAttributeMaxDynamicSharedMemorySize, SMEM);

    int nb = (n + 2047) / 2048;
    int gb = (n + 63) / 64;
    int nb2 = (n + 31) / 32;

    // fork: preprocessing (edge-index work) on side stream, GEMM path on main
    static cudaStream_t sside = nullptr;
    static cudaEvent_t evFork = nullptr, evJoin = nullptr;
    if (!sside) {
        cudaStreamCreateWithFlags(&sside, cudaStreamNonBlocking);
        cudaEventCreateWithFlags(&evFork, cudaEventDisableTiming);
        cudaEventCreateWithFlags(&evJoin, cudaEventDisableTiming);
    }

    cudaEventRecord(evFork, 0);
    cudaStreamWaitEvent(sside, evFork, 0);

    // main: prepack1 + gemm_l1 (prepack2 deferred to after gemm_l1)
    prepack1<<<(4 * 4 * 16 * 128 + 255) / 256, 256>>>(Wq1, Wk1, Wv1, Ws1);
    init_kernel<<<(n + 256) / 256, 256, 0, sside>>>((const int*)ei, n);
    hist_kernel<<<(E + 255) / 256, 256, 0, sside>>>(ei, E);
    gemm_l1<<<dim3(gb, 4), 256, SMEM>>>(x, bq1, bk1, bv1, bs1,
                                        q1b, (unsigned*)kv1, s1, n);   // launch #4
    prepack2<<<(4 * 16 * 128 + 255) / 256, 256>>>(Wq2, Wk2, Wv2, Ws2);
    // side: rest of preprocessing
    scan_phase1<<<nb, 256, 0, sside>>>(n);
    scan_phase3<<<(n + 255) / 256, 256, 0, sside>>>(n, nb);
    fill_kernel<<<(E + 255) / 256, 256, 0, sside>>>(ei, E);
    cudaEventRecord(evJoin, sside);

    cudaStreamWaitEvent(0, evJoin, 0);   // join before attention

    edge_attn1<<<(n * 32 + 255) / 256, 256>>>(q1b, kv1, s1, h1, n);
    gemm_l2<<<gb, 256, SMEM>>>(h1, bq2, bk2, bv2, bs2,
                               q2b, (unsigned*)kv2, s2, n);
    edge_attn2<<<nb2, 256>>>(q2b, kv2, s2, part, n);
    final_kernel<<<1, 1024>>>(Wo, bo, out, n, nb2);
}